// round 5
// baseline (speedup 1.0000x reference)
#include <cuda_runtime.h>
#include <cuda_fp16.h>
#include <cstdint>

// Problem dims
constexpr int cB = 128;
constexpr int cT = 256;
constexpr int cH = 1024;
constexpr int cV = 4096;

// Fused persistent kernel layout
constexpr int GRID_F = 148;          // one CTA per SM (single wave; SMEM forces 1/SM)
constexpr int NREC   = 96;           // 32 layer0 + 64 layer1 recurrence CTAs
constexpr int NL0    = 32;
constexpr int NTILES = (cT * cB / 128) * (cV / 128);   // 8192 output tiles

// Recurrence SMEM
constexpr int L0_PAD_H = 1032;       // weight row stride halves (2064 B)
constexpr int L1_PAD_H = 2056;       // (4112 B)
constexpr int W_HALVES  = 32 * L0_PAD_H;      // 33024 halves (covers L1: 16*2056=32896)
constexpr int ACH_PAD   = 136;                // A-chunk row stride halves (272 B)
constexpr int ACH_HALVES = 128 * ACH_PAD;     // 17408 halves per buffer
constexpr int NBUF = 4;                       // cp.async ring depth
constexpr int SMEM_F = (W_HALVES + NBUF * ACH_HALVES) * 2;  // 205312 B

// Output-GEMM worker staging (fits inside SMEM_F)
constexpr int KO_ROW = 72;                    // 64 + 8 pad halves (144 B row stride)
constexpr int KO_BUF = 128 * KO_ROW;          // 9216 halves per buffer

// ---------------- device globals ----------------
__device__ __half g_Whh0[cH * cH];            // [j][k]
__device__ __half g_W1[cH * 2048];            // [j][k]: k<1024 W_ih1, k>=1024 W_hh1
__device__ __half g_Wfc[cV * cH];             // [v][k]
__device__ float  g_w0[cH], g_b0[cH], g_b1[cH];
__device__ float  g_xT[cT * cB];              // x transposed [t][b]
__device__ __half g_h0[2][cB * cH];
__device__ __half g_h1[2][cB * cH];
__device__ float  g_h0f[cB * cH], g_h1f[cB * cH];
__device__ __half g_H1[(size_t)cT * cB * cH]; // h1 history [t][b][h]
__device__ unsigned g_bar_count = 0;
__device__ unsigned g_bar_gen   = 0;
__device__ unsigned g_stage_done = 0;         // monotone stages-completed counter
__device__ unsigned g_tile = 0;               // output-tile work queue

// ---------------- helpers ----------------
__device__ __forceinline__ uint32_t smem_u32(const void* p) {
    uint32_t a;
    asm("{ .reg .u64 t; cvta.to.shared.u64 t, %1; cvt.u32.u64 %0, t; }" : "=r"(a) : "l"(p));
    return a;
}
__device__ __forceinline__ void cp16(uint32_t dst, const void* src) {
    asm volatile("cp.async.cg.shared.global [%0], [%1], 16;\n" :: "r"(dst), "l"(src));
}
#define CP_COMMIT() asm volatile("cp.async.commit_group;\n")
#define CP_WAIT(n)  asm volatile("cp.async.wait_group %0;\n" :: "n"(n))

__device__ __forceinline__ void ldsm4(unsigned r[4], uint32_t a) {
    asm volatile("ldmatrix.sync.aligned.m8n8.x4.shared.b16 {%0,%1,%2,%3}, [%4];"
        : "=r"(r[0]), "=r"(r[1]), "=r"(r[2]), "=r"(r[3]) : "r"(a));
}
__device__ __forceinline__ void mma_m16n8k16(float c[4], const unsigned a[4],
                                             unsigned b0, unsigned b1) {
    asm volatile(
        "mma.sync.aligned.m16n8k16.row.col.f32.f16.f16.f32 "
        "{%0,%1,%2,%3}, {%4,%5,%6,%7}, {%8,%9}, {%0,%1,%2,%3};\n"
        : "+f"(c[0]), "+f"(c[1]), "+f"(c[2]), "+f"(c[3])
        : "r"(a[0]), "r"(a[1]), "r"(a[2]), "r"(a[3]), "r"(b0), "r"(b1));
}

// ---------------- grid barrier over the 96 recurrence CTAs ----------------
__device__ __forceinline__ void grid_barrier(unsigned target, unsigned done) {
    __syncthreads();
    if (threadIdx.x == 0) {
        __threadfence();  // release
        unsigned t = atomicAdd(&g_bar_count, 1);
        if (t == NREC - 1) {
            *(volatile unsigned*)&g_bar_count = 0;
            __threadfence();
            *(volatile unsigned*)&g_stage_done = done;   // monotone progress for workers
            *(volatile unsigned*)&g_bar_gen = target;
        } else {
            while (*(volatile unsigned*)&g_bar_gen != target) { __nanosleep(32); }
        }
        __threadfence();  // acquire
    }
    __syncthreads();
}

// ---------------- prep ----------------
__global__ void k_prep(const float* __restrict__ x,
                       const float* __restrict__ Wih0, const float* __restrict__ Whh0,
                       const float* __restrict__ bih0, const float* __restrict__ bhh0,
                       const float* __restrict__ Wih1, const float* __restrict__ Whh1,
                       const float* __restrict__ bih1, const float* __restrict__ bhh1,
                       const float* __restrict__ Wfc) {
    const long long i = (long long)blockIdx.x * blockDim.x + threadIdx.x;
    const long long stride = (long long)gridDim.x * blockDim.x;
    if (i == 0) {
        g_bar_count = 0; g_bar_gen = 0; g_stage_done = 0; g_tile = 0;
    }
    for (long long idx = i; idx < (long long)cH * cH; idx += stride) {
        g_Whh0[idx] = __float2half_rn(Whh0[idx]);
        const int j = (int)(idx >> 10), k = (int)(idx & 1023);
        g_W1[(size_t)j * 2048 + k]        = __float2half_rn(Wih1[idx]);
        g_W1[(size_t)j * 2048 + 1024 + k] = __float2half_rn(Whh1[idx]);
    }
    for (long long idx = i; idx < (long long)cV * cH; idx += stride)
        g_Wfc[idx] = __float2half_rn(Wfc[idx]);
    for (long long idx = i; idx < cH; idx += stride) {
        g_w0[idx] = Wih0[idx];
        g_b0[idx] = bih0[idx] + bhh0[idx];
        g_b1[idx] = bih1[idx] + bhh1[idx];
    }
    for (long long idx = i; idx < (long long)cB * cT; idx += stride) {
        const int b = (int)(idx >> 8), t = (int)(idx & 255);   // x: [B][1][T]
        g_xT[t * cB + b] = x[idx];
    }
    const __half z = __float2half(0.f);
    for (long long idx = i; idx < (long long)cB * cH; idx += stride) {
        g_h0[0][idx] = z; g_h0[1][idx] = z;
        g_h1[0][idx] = z; g_h1[1][idx] = z;
    }
}

// ---------------- output-GEMM worker (runs inside fused kernel) ----------------
// 128x128 tiles off the g_tile queue, gated on recurrence progress.
// Depth-4 cp.async ring over K-chunks of 64 halves.
__device__ void gemm_worker(char* smem, const float* __restrict__ bfc,
                            float* __restrict__ out) {
    uint32_t dA[NBUF], dB[NBUF];
    #pragma unroll
    for (int v = 0; v < NBUF; ++v) {
        dA[v] = smem_u32((__half*)smem + v * KO_BUF);
        dB[v] = smem_u32((__half*)smem + (NBUF + v) * KO_BUF);
    }

    __shared__ unsigned s_tile;
    const int tid = threadIdx.x, warp = tid >> 5, lane = tid & 31;
    const int gr = lane >> 2, q = lane & 3;
    const int wm = warp & 3, wn = warp >> 2;
    const int r0 = wm * 32;       // local M offset
    const int v0l = wn * 64;      // local N offset
    const int lrow = (lane & 7) | (lane & 8);
    const int lc16 = (lane >> 4) & 1;
    const int st_r = tid >> 3;    // staging: rows st_r + j*32
    const int st_c = tid & 7;

    for (;;) {
        __syncthreads();
        if (tid == 0) s_tile = atomicAdd(&g_tile, 1);
        __syncthreads();
        const unsigned idx = s_tile;
        if (idx >= NTILES) break;
        const int ntile = idx & 31;
        const int mtile = (int)(idx >> 5);          // == t
        // gate: h1(t) published once stage t+1 completes -> done counter t+2
        if (tid == 0) {
            const unsigned need = (unsigned)(mtile + 2);
            while (*(volatile unsigned*)&g_stage_done < need) { __nanosleep(64); }
            __threadfence();
        }
        __syncthreads();

        const uint4* gA = (const uint4*)g_H1 + (size_t)(mtile * 128) * 128;
        const uint4* gB = (const uint4*)g_Wfc + (size_t)(ntile * 128) * 128;

        // prefetch chunks 0..2
        #pragma unroll
        for (int pc = 0; pc < NBUF - 1; ++pc) {
            #pragma unroll
            for (int j = 0; j < 4; ++j) {
                const int r = st_r + j * 32;
                cp16(dA[pc] + (uint32_t)(r * 9 + st_c) * 16, gA + r * 128 + pc * 8 + st_c);
                cp16(dB[pc] + (uint32_t)(r * 9 + st_c) * 16, gB + r * 128 + pc * 8 + st_c);
            }
            CP_COMMIT();
        }

        float c[2][8][4] = {};
        #pragma unroll 1
        for (int kc = 0; kc < 16; ++kc) {
            CP_WAIT(NBUF - 2);
            __syncthreads();
            const uint32_t Ab = dA[kc & (NBUF - 1)] + (uint32_t)((r0 + lrow) * 144 + lc16 * 16);
            const uint32_t Bb = dB[kc & (NBUF - 1)] + (uint32_t)((v0l + lrow) * 144 + lc16 * 16);
            #pragma unroll
            for (int i = 0; i < 4; ++i) {
                unsigned a[2][4];
                ldsm4(a[0], Ab + i * 32);
                ldsm4(a[1], Ab + 16 * 144 + i * 32);
                #pragma unroll
                for (int np = 0; np < 4; ++np) {
                    unsigned b[4];
                    ldsm4(b, Bb + np * (16 * 144) + i * 32);
                    mma_m16n8k16(c[0][2 * np],     a[0], b[0], b[2]);
                    mma_m16n8k16(c[0][2 * np + 1], a[0], b[1], b[3]);
                    mma_m16n8k16(c[1][2 * np],     a[1], b[0], b[2]);
                    mma_m16n8k16(c[1][2 * np + 1], a[1], b[1], b[3]);
                }
            }
            __syncthreads();
            const int kn = kc + NBUF - 1;
            if (kn < 16) {
                #pragma unroll
                for (int j = 0; j < 4; ++j) {
                    const int r = st_r + j * 32;
                    cp16(dA[kn & (NBUF - 1)] + (uint32_t)(r * 9 + st_c) * 16,
                         gA + r * 128 + kn * 8 + st_c);
                    cp16(dB[kn & (NBUF - 1)] + (uint32_t)(r * 9 + st_c) * 16,
                         gB + r * 128 + kn * 8 + st_c);
                }
            }
            CP_COMMIT();   // may be empty: keeps group accounting uniform
        }

        #pragma unroll
        for (int m = 0; m < 2; ++m) {
            #pragma unroll
            for (int nf = 0; nf < 8; ++nf) {
                const int v = ntile * 128 + v0l + nf * 8 + 2 * q;
                const float bf0 = bfc[v], bf1 = bfc[v + 1];
                const int rA = mtile * 128 + r0 + m * 16 + gr;
                {   // r = t*B + b -> out[(b*T + t)*V + v]
                    const int t = rA >> 7, b = rA & 127;
                    *(float2*)(out + (size_t)(b * cT + t) * cV + v) =
                        make_float2(c[m][nf][0] + bf0, c[m][nf][1] + bf1);
                }
                {
                    const int rB = rA + 8;
                    const int t = rB >> 7, b = rB & 127;
                    *(float2*)(out + (size_t)(b * cT + t) * cV + v) =
                        make_float2(c[m][nf][2] + bf0, c[m][nf][3] + bf1);
                }
            }
        }
    }
}

// ---------------- fused persistent kernel ----------------
// CTAs 0..95: pipelined 2-layer recurrence (then join GEMM queue).
// CTAs 96..147: output-GEMM workers from the start, gated on stage progress.
__global__ void __launch_bounds__(256, 1) k_fused(const float* __restrict__ bfc,
                                                  float* __restrict__ out) {
    extern __shared__ char smem_raw[];
    const int bx = blockIdx.x;
    const int tid = threadIdx.x;

    if (bx >= NREC) {
        gemm_worker(smem_raw, bfc, out);
        return;
    }

    __half* sW = (__half*)smem_raw;
    const bool isL0 = (bx < NL0);

    // Preload this CTA's stationary weight slice into padded SMEM
    if (isL0) {
        const uint4* src = (const uint4*)(g_Whh0 + (size_t)bx * 32 * cH);
        for (int v = tid; v < 32 * 128; v += 256) {
            const int jl = v >> 7, c = v & 127;
            ((uint4*)(sW + jl * L0_PAD_H))[c] = src[jl * 128 + c];
        }
    } else {
        const uint4* src = (const uint4*)(g_W1 + (size_t)(bx - NL0) * 16 * 2048);
        for (int v = tid; v < 16 * 256; v += 256) {
            const int jl = v >> 8, c = v & 255;
            ((uint4*)(sW + jl * L1_PAD_H))[c] = src[jl * 256 + c];
        }
    }
    __syncthreads();

    uint32_t sAdst[NBUF];
    #pragma unroll
    for (int v = 0; v < NBUF; ++v)
        sAdst[v] = smem_u32(sW + W_HALVES + v * ACH_HALVES);
    const uint32_t wB = smem_u32(sW);
    const int warp = tid >> 5, lane = tid & 31;
    const int gr = lane >> 2, q = lane & 3;
    const int r0 = warp * 16;                 // 8 warps cover M=128
    const int lrow = (lane & 7) | (lane & 8);
    const int lc16 = (lane >> 4) & 1;
    const uint32_t aOff = (uint32_t)((r0 + lrow) * 272 + lc16 * 16);
    uint32_t aBase[NBUF];
    #pragma unroll
    for (int v = 0; v < NBUF; ++v) aBase[v] = sAdst[v] + aOff;
    // ldmatrix weight bases
    const uint32_t bL0_0 = wB + (uint32_t)(lrow * 2064 + lc16 * 16);           // j 0..15
    const uint32_t bL0_1 = wB + (uint32_t)((16 + lrow) * 2064 + lc16 * 16);    // j 16..31
    const uint32_t bL1   = wB + (uint32_t)(lrow * 4112 + lc16 * 16);           // j 0..15
    const int st_r = tid >> 4;                // staging rows st_r + j*16
    const int st_c = tid & 15;

    for (int s = 0; s <= cT; ++s) {
        const int p = s & 1;
        if (isL0) {
            if (s < cT) {
                const uint4* gsrc = (const uint4*)g_h0[p];
                // prefetch chunks 0..2
                #pragma unroll
                for (int pc = 0; pc < NBUF - 1; ++pc) {
                    #pragma unroll
                    for (int j = 0; j < 8; ++j) {
                        const int r = st_r + j * 16;
                        cp16(sAdst[pc] + (uint32_t)(r * 17 + st_c) * 16,
                             gsrc + r * 128 + pc * 16 + st_c);
                    }
                    CP_COMMIT();
                }
                float c[4][4] = {};
                #pragma unroll 1
                for (int kc = 0; kc < 8; ++kc) {
                    CP_WAIT(NBUF - 2);
                    __syncthreads();
                    const uint32_t Ab = aBase[kc & (NBUF - 1)];
                    const uint32_t kcb = (uint32_t)kc * 256;
                    #pragma unroll
                    for (int i = 0; i < 8; ++i) {
                        unsigned a[4], b0[4], b1[4];
                        ldsm4(a, Ab + i * 32);
                        ldsm4(b0, bL0_0 + kcb + i * 32);
                        ldsm4(b1, bL0_1 + kcb + i * 32);
                        mma_m16n8k16(c[0], a, b0[0], b0[2]);
                        mma_m16n8k16(c[1], a, b0[1], b0[3]);
                        mma_m16n8k16(c[2], a, b1[0], b1[2]);
                        mma_m16n8k16(c[3], a, b1[1], b1[3]);
                    }
                    __syncthreads();
                    const int kn = kc + NBUF - 1;
                    if (kn < 8) {
                        #pragma unroll
                        for (int j = 0; j < 8; ++j) {
                            const int r = st_r + j * 16;
                            cp16(sAdst[kn & (NBUF - 1)] + (uint32_t)(r * 17 + st_c) * 16,
                                 gsrc + r * 128 + kn * 16 + st_c);
                        }
                    }
                    CP_COMMIT();   // may be empty
                }
                // epilogue
                const int jb = bx * 32;
                const int row0 = r0 + gr, row8 = row0 + 8;
                const float xv0 = g_xT[s * cB + row0];
                const float xv8 = g_xT[s * cB + row8];
                __half* outh = g_h0[1 - p];
                const bool fin = (s == cT - 1);
                #pragma unroll
                for (int nf = 0; nf < 4; ++nf) {
                    const int j = jb + nf * 8 + 2 * q;
                    const float w0a = g_w0[j], w0b = g_w0[j + 1];
                    const float ba = g_b0[j], bb = g_b0[j + 1];
                    const float h00 = tanhf(c[nf][0] + xv0 * w0a + ba);
                    const float h01 = tanhf(c[nf][1] + xv0 * w0b + bb);
                    const float h08 = tanhf(c[nf][2] + xv8 * w0a + ba);
                    const float h09 = tanhf(c[nf][3] + xv8 * w0b + bb);
                    const int i0 = row0 * cH + j;
                    const int i8 = row8 * cH + j;
                    *(__half2*)(outh + i0) = __floats2half2_rn(h00, h01);
                    *(__half2*)(outh + i8) = __floats2half2_rn(h08, h09);
                    if (fin) {
                        *(float2*)(g_h0f + i0) = make_float2(h00, h01);
                        *(float2*)(g_h0f + i8) = make_float2(h08, h09);
                    }
                }
            }
        } else {
            if (s >= 1) {
                // prefetch chunks 0..2 (all from h0 half: kn<8)
                {
                    const uint4* gsrc = (const uint4*)g_h0[p];
                    #pragma unroll
                    for (int pc = 0; pc < NBUF - 1; ++pc) {
                        #pragma unroll
                        for (int j = 0; j < 8; ++j) {
                            const int r = st_r + j * 16;
                            cp16(sAdst[pc] + (uint32_t)(r * 17 + st_c) * 16,
                                 gsrc + r * 128 + pc * 16 + st_c);
                        }
                        CP_COMMIT();
                    }
                }
                float c[2][4] = {};
                #pragma unroll 1
                for (int kc = 0; kc < 16; ++kc) {
                    CP_WAIT(NBUF - 2);
                    __syncthreads();
                    const uint32_t Ab = aBase[kc & (NBUF - 1)];
                    const uint32_t kcb = (uint32_t)kc * 256;
                    #pragma unroll
                    for (int i = 0; i < 8; ++i) {
                        unsigned a[4], b[4];
                        ldsm4(a, Ab + i * 32);
                        ldsm4(b, bL1 + kcb + i * 32);
                        mma_m16n8k16(c[0], a, b[0], b[2]);
                        mma_m16n8k16(c[1], a, b[1], b[3]);
                    }
                    __syncthreads();
                    const int kn = kc + NBUF - 1;
                    if (kn < 16) {
                        const uint4* gsrc = (kn < 8) ? (const uint4*)g_h0[p]
                                                     : (const uint4*)g_h1[p];
                        const int kloc = kn & 7;
                        #pragma unroll
                        for (int j = 0; j < 8; ++j) {
                            const int r = st_r + j * 16;
                            cp16(sAdst[kn & (NBUF - 1)] + (uint32_t)(r * 17 + st_c) * 16,
                                 gsrc + r * 128 + kloc * 16 + st_c);
                        }
                    }
                    CP_COMMIT();   // may be empty
                }
                // epilogue
                const int jb = (bx - NL0) * 16;
                const int row0 = r0 + gr, row8 = row0 + 8;
                __half* outh = g_h1[1 - p];
                __half* H1t = g_H1 + (size_t)(s - 1) * cB * cH;
                const bool fin = (s == cT);
                #pragma unroll
                for (int nf = 0; nf < 2; ++nf) {
                    const int j = jb + nf * 8 + 2 * q;
                    const float ba = g_b1[j], bb = g_b1[j + 1];
                    const float h10 = tanhf(c[nf][0] + ba);
                    const float h11 = tanhf(c[nf][1] + bb);
                    const float h12 = tanhf(c[nf][2] + ba);
                    const float h13 = tanhf(c[nf][3] + bb);
                    const int i0 = row0 * cH + j;
                    const int i8 = row8 * cH + j;
                    const __half2 lo = __floats2half2_rn(h10, h11);
                    const __half2 hi = __floats2half2_rn(h12, h13);
                    *(__half2*)(outh + i0) = lo;
                    *(__half2*)(outh + i8) = hi;
                    *(__half2*)(H1t + i0) = lo;
                    *(__half2*)(H1t + i8) = hi;
                    if (fin) {
                        *(float2*)(g_h1f + i0) = make_float2(h10, h11);
                        *(float2*)(g_h1f + i8) = make_float2(h12, h13);
                    }
                }
            }
        }
        grid_barrier((s == cT) ? 0u : (unsigned)(s + 1), (unsigned)(s + 1));
    }

    // recurrence done -> help drain the output-GEMM queue
    gemm_worker(smem_raw, bfc, out);
}

// ---------------- final hidden states tail: [2][B][H] fp32 ----------------
__global__ void k_states(float* __restrict__ out) {
    const int i = blockIdx.x * blockDim.x + threadIdx.x;
    if (i < cB * cH) {
        out[(size_t)cB * cT * cV + i] = g_h0f[i];
        out[(size_t)cB * cT * cV + cB * cH + i] = g_h1f[i];
    }
}

extern "C" void kernel_launch(void* const* d_in, const int* in_sizes, int n_in,
                              void* d_out, int out_size) {
    const float* x    = (const float*)d_in[0];
    const float* Wih0 = (const float*)d_in[1];
    const float* Whh0 = (const float*)d_in[2];
    const float* bih0 = (const float*)d_in[3];
    const float* bhh0 = (const float*)d_in[4];
    const float* Wih1 = (const float*)d_in[5];
    const float* Whh1 = (const float*)d_in[6];
    const float* bih1 = (const float*)d_in[7];
    const float* bhh1 = (const float*)d_in[8];
    const float* Wfc  = (const float*)d_in[9];
    const float* bfc  = (const float*)d_in[10];
    float* out = (float*)d_out;

    cudaFuncSetAttribute(k_fused, cudaFuncAttributeMaxDynamicSharedMemorySize, SMEM_F);

    k_prep<<<1024, 256>>>(x, Wih0, Whh0, bih0, bhh0, Wih1, Whh1, bih1, bhh1, Wfc);
    k_fused<<<GRID_F, 256, SMEM_F>>>(bfc, out);

    const long long need = (long long)cB * cT * cV + 2LL * cB * cH;
    if ((long long)out_size >= need)
        k_states<<<(cB * cH + 255) / 256, 256>>>(out);
}

// round 6
// speedup vs baseline: 1.0601x; 1.0601x over previous
#include <cuda_runtime.h>
#include <cuda_fp16.h>
#include <cstdint>

// Problem dims
constexpr int cB = 128;
constexpr int cT = 256;
constexpr int cH = 1024;
constexpr int cV = 4096;

// Fused persistent kernel layout
constexpr int GRID_F = 148;          // one CTA per SM
constexpr int NREC   = 96;           // 32 layer0 + 64 layer1 recurrence CTAs
constexpr int NL0    = 32;
constexpr int NTILES = (cT * cB / 128) * (cV / 128);   // 8192 output tiles

// Recurrence SMEM
constexpr int L0_PAD_H = 1032;       // weight row stride halves (2064 B)
constexpr int L1_PAD_H = 2056;       // (4112 B)
constexpr int W_HALVES  = 32 * L0_PAD_H;      // 33024 halves (covers L1: 16*2056=32896)
constexpr int ACH_PAD   = 136;                // A-chunk row stride halves (272 B)
constexpr int ACH_HALVES = 128 * ACH_PAD;     // 17408 halves per buffer
constexpr int NBUF = 3;                       // cp.async ring depth (1 sync/chunk)
constexpr int SMEM_F = (W_HALVES + NBUF * ACH_HALVES) * 2;  // 170496 B

// Output-GEMM worker staging (fits inside SMEM_F)
constexpr int KO_ROW = 72;                    // 64 + 8 pad halves (144 B row stride)
constexpr int KO_BUF = 128 * KO_ROW;          // 9216 halves per buffer

// ---------------- device globals ----------------
__device__ __half g_Whh0[cH * cH];            // [j][k]
__device__ __half g_W1[cH * 2048];            // [j][k]: k<1024 W_ih1, k>=1024 W_hh1
__device__ __half g_Wfc[cV * cH];             // [v][k]
__device__ float  g_w0[cH], g_b0[cH], g_b1[cH];
__device__ float  g_xT[cT * cB];              // x transposed [t][b]
__device__ __half g_h0[2][cB * cH];
__device__ __half g_h1[2][cB * cH];
__device__ float  g_h0f[cB * cH], g_h1f[cB * cH];
__device__ __half g_H1[(size_t)cT * cB * cH]; // h1 history [t][b][h]
__device__ unsigned g_bar_count = 0;
__device__ unsigned g_bar_gen   = 0;
__device__ unsigned g_stage_done = 0;         // monotone stages-completed counter
__device__ unsigned g_tile = 0;               // output-tile work queue

// ---------------- helpers ----------------
__device__ __forceinline__ uint32_t smem_u32(const void* p) {
    uint32_t a;
    asm("{ .reg .u64 t; cvta.to.shared.u64 t, %1; cvt.u32.u64 %0, t; }" : "=r"(a) : "l"(p));
    return a;
}
__device__ __forceinline__ void cp16(uint32_t dst, const void* src) {
    asm volatile("cp.async.cg.shared.global [%0], [%1], 16;\n" :: "r"(dst), "l"(src));
}
#define CP_COMMIT() asm volatile("cp.async.commit_group;\n")
#define CP_WAIT(n)  asm volatile("cp.async.wait_group %0;\n" :: "n"(n))

__device__ __forceinline__ void ldsm4(unsigned r[4], uint32_t a) {
    asm volatile("ldmatrix.sync.aligned.m8n8.x4.shared.b16 {%0,%1,%2,%3}, [%4];"
        : "=r"(r[0]), "=r"(r[1]), "=r"(r[2]), "=r"(r[3]) : "r"(a));
}
__device__ __forceinline__ void mma_m16n8k16(float c[4], const unsigned a[4],
                                             unsigned b0, unsigned b1) {
    asm volatile(
        "mma.sync.aligned.m16n8k16.row.col.f32.f16.f16.f32 "
        "{%0,%1,%2,%3}, {%4,%5,%6,%7}, {%8,%9}, {%0,%1,%2,%3};\n"
        : "+f"(c[0]), "+f"(c[1]), "+f"(c[2]), "+f"(c[3])
        : "r"(a[0]), "r"(a[1]), "r"(a[2]), "r"(a[3]), "r"(b0), "r"(b1));
}

// acquire/release primitives (avoid full MEMBAR.GL)
__device__ __forceinline__ unsigned atom_add_release(unsigned* p, unsigned v) {
    unsigned r;
    asm volatile("atom.add.release.gpu.u32 %0, [%1], %2;" : "=r"(r) : "l"(p), "r"(v) : "memory");
    return r;
}
__device__ __forceinline__ unsigned ld_acquire(const unsigned* p) {
    unsigned r;
    asm volatile("ld.acquire.gpu.u32 %0, [%1];" : "=r"(r) : "l"(p) : "memory");
    return r;
}
__device__ __forceinline__ void st_release(unsigned* p, unsigned v) {
    asm volatile("st.release.gpu.u32 [%0], %1;" :: "l"(p), "r"(v) : "memory");
}

// ---------------- grid barrier (generalized CTA count) ----------------
__device__ __forceinline__ void grid_barrier(int nct, unsigned target, unsigned done) {
    __syncthreads();
    if (threadIdx.x == 0) {
        const unsigned t = atom_add_release(&g_bar_count, 1);   // release: my prior stores
        if (t == (unsigned)nct - 1) {
            *(volatile unsigned*)&g_bar_count = 0;
            st_release(&g_stage_done, done);
            st_release(&g_bar_gen, target);
        } else {
            while (ld_acquire(&g_bar_gen) != target) { __nanosleep(32); }
        }
    }
    __syncthreads();
}

// ---------------- output-GEMM worker (inside fused kernel) ----------------
// 128x128 tiles off the g_tile queue, gated on recurrence progress.
__device__ void gemm_worker(char* smem, const float* __restrict__ bfc,
                            float* __restrict__ out) {
    uint32_t dA[NBUF], dB[NBUF];
    #pragma unroll
    for (int v = 0; v < NBUF; ++v) {
        dA[v] = smem_u32((__half*)smem + v * KO_BUF);
        dB[v] = smem_u32((__half*)smem + (NBUF + v) * KO_BUF);
    }

    __shared__ unsigned s_tile;
    const int tid = threadIdx.x, warp = tid >> 5, lane = tid & 31;
    const int gr = lane >> 2, q = lane & 3;
    const int wm = warp & 3, wn = warp >> 2;
    const int r0 = wm * 32;       // local M offset
    const int v0l = wn * 64;      // local N offset
    const int lrow = (lane & 7) | (lane & 8);
    const int lc16 = (lane >> 4) & 1;
    const int st_r = tid >> 3;    // staging: rows st_r + j*32
    const int st_c = tid & 7;

    for (;;) {
        __syncthreads();
        if (tid == 0) s_tile = atomicAdd(&g_tile, 1);
        __syncthreads();
        const unsigned idx = s_tile;
        if (idx >= NTILES) break;
        const int ntile = idx & 31;
        const int mtile = (int)(idx >> 5);          // == t
        // gate: h1(t) published once stage t+1 completes -> done counter t+2
        if (tid == 0) {
            const unsigned need = (unsigned)(mtile + 2);
            while (ld_acquire(&g_stage_done) < need) { __nanosleep(64); }
        }
        __syncthreads();

        const uint4* gA = (const uint4*)g_H1 + (size_t)(mtile * 128) * 128;
        const uint4* gB = (const uint4*)g_Wfc + (size_t)(ntile * 128) * 128;

        // prefetch chunks 0,1
        #pragma unroll
        for (int pc = 0; pc < 2; ++pc) {
            #pragma unroll
            for (int j = 0; j < 4; ++j) {
                const int r = st_r + j * 32;
                cp16(dA[pc] + (uint32_t)(r * 9 + st_c) * 16, gA + r * 128 + pc * 8 + st_c);
                cp16(dB[pc] + (uint32_t)(r * 9 + st_c) * 16, gB + r * 128 + pc * 8 + st_c);
            }
            CP_COMMIT();
        }

        float c[2][8][4] = {};
        #pragma unroll 1
        for (int kc = 0; kc < 16; ++kc) {
            CP_WAIT(1);
            __syncthreads();
            const int kn = kc + 2;
            if (kn < 16) {
                const uint32_t da = dA[kn % NBUF], db = dB[kn % NBUF];
                #pragma unroll
                for (int j = 0; j < 4; ++j) {
                    const int r = st_r + j * 32;
                    cp16(da + (uint32_t)(r * 9 + st_c) * 16, gA + r * 128 + kn * 8 + st_c);
                    cp16(db + (uint32_t)(r * 9 + st_c) * 16, gB + r * 128 + kn * 8 + st_c);
                }
            }
            CP_COMMIT();   // may be empty: uniform group accounting
            const uint32_t Ab = dA[kc % NBUF] + (uint32_t)((r0 + lrow) * 144 + lc16 * 16);
            const uint32_t Bb = dB[kc % NBUF] + (uint32_t)((v0l + lrow) * 144 + lc16 * 16);
            #pragma unroll
            for (int i = 0; i < 4; ++i) {
                unsigned a[2][4];
                ldsm4(a[0], Ab + i * 32);
                ldsm4(a[1], Ab + 16 * 144 + i * 32);
                #pragma unroll
                for (int np = 0; np < 4; ++np) {
                    unsigned b[4];
                    ldsm4(b, Bb + np * (16 * 144) + i * 32);
                    mma_m16n8k16(c[0][2 * np],     a[0], b[0], b[2]);
                    mma_m16n8k16(c[0][2 * np + 1], a[0], b[1], b[3]);
                    mma_m16n8k16(c[1][2 * np],     a[1], b[0], b[2]);
                    mma_m16n8k16(c[1][2 * np + 1], a[1], b[1], b[3]);
                }
            }
        }

        #pragma unroll
        for (int m = 0; m < 2; ++m) {
            #pragma unroll
            for (int nf = 0; nf < 8; ++nf) {
                const int v = ntile * 128 + v0l + nf * 8 + 2 * q;
                const float bf0 = bfc[v], bf1 = bfc[v + 1];
                const int rA = mtile * 128 + r0 + m * 16 + gr;
                {   // r = t*B + b -> out[(b*T + t)*V + v]
                    const int t = rA >> 7, b = rA & 127;
                    *(float2*)(out + (size_t)(b * cT + t) * cV + v) =
                        make_float2(c[m][nf][0] + bf0, c[m][nf][1] + bf1);
                }
                {
                    const int rB = rA + 8;
                    const int t = rB >> 7, b = rB & 127;
                    *(float2*)(out + (size_t)(b * cT + t) * cV + v) =
                        make_float2(c[m][nf][2] + bf0, c[m][nf][3] + bf1);
                }
            }
        }
    }
}

// ---------------- single fused persistent kernel ----------------
// Phase 0: all 148 CTAs convert weights (grid-stride) -> 148-CTA barrier.
// Then CTAs 0..95 run the recurrence (stage barrier over 96), CTAs 96..147 are
// output-GEMM workers. Recurrence CTAs 0..7 write final states, then all join
// the GEMM queue until drained.
__global__ void __launch_bounds__(256, 1) k_fused(
    const float* __restrict__ x,
    const float* __restrict__ Wih0, const float* __restrict__ Whh0,
    const float* __restrict__ bih0, const float* __restrict__ bhh0,
    const float* __restrict__ Wih1, const float* __restrict__ Whh1,
    const float* __restrict__ bih1, const float* __restrict__ bhh1,
    const float* __restrict__ Wfc,  const float* __restrict__ bfc,
    float* __restrict__ out, int do_states) {
    extern __shared__ char smem_raw[];
    const int bx = blockIdx.x;
    const int tid = threadIdx.x;

    // ---- phase 0: prep (all CTAs) ----
    {
        const long long i = (long long)bx * blockDim.x + tid;
        const long long stride = (long long)GRID_F * 256;
        if (i == 0) { g_tile = 0; *(volatile unsigned*)&g_stage_done = 0; }
        for (long long idx = i; idx < (long long)cH * cH; idx += stride) {
            g_Whh0[idx] = __float2half_rn(Whh0[idx]);
            const int j = (int)(idx >> 10), k = (int)(idx & 1023);
            g_W1[(size_t)j * 2048 + k]        = __float2half_rn(Wih1[idx]);
            g_W1[(size_t)j * 2048 + 1024 + k] = __float2half_rn(Whh1[idx]);
        }
        for (long long idx = i; idx < (long long)cV * cH; idx += stride)
            g_Wfc[idx] = __float2half_rn(Wfc[idx]);
        for (long long idx = i; idx < cH; idx += stride) {
            g_w0[idx] = Wih0[idx];
            g_b0[idx] = bih0[idx] + bhh0[idx];
            g_b1[idx] = bih1[idx] + bhh1[idx];
        }
        for (long long idx = i; idx < (long long)cB * cT; idx += stride) {
            const int b = (int)(idx >> 8), t = (int)(idx & 255);   // x: [B][1][T]
            g_xT[t * cB + b] = x[idx];
        }
        const __half z = __float2half(0.f);
        for (long long idx = i; idx < (long long)cB * cH; idx += stride) {
            g_h0[0][idx] = z; g_h0[1][idx] = z;
            g_h1[0][idx] = z; g_h1[1][idx] = z;
        }
    }
    grid_barrier(GRID_F, 1u, 0u);

    if (bx >= NREC) {
        gemm_worker(smem_raw, bfc, out);
        return;
    }

    __half* sW = (__half*)smem_raw;
    const bool isL0 = (bx < NL0);

    // Preload this CTA's stationary weight slice into padded SMEM
    if (isL0) {
        const uint4* src = (const uint4*)(g_Whh0 + (size_t)bx * 32 * cH);
        for (int v = tid; v < 32 * 128; v += 256) {
            const int jl = v >> 7, c = v & 127;
            ((uint4*)(sW + jl * L0_PAD_H))[c] = src[jl * 128 + c];
        }
    } else {
        const uint4* src = (const uint4*)(g_W1 + (size_t)(bx - NL0) * 16 * 2048);
        for (int v = tid; v < 16 * 256; v += 256) {
            const int jl = v >> 8, c = v & 255;
            ((uint4*)(sW + jl * L1_PAD_H))[c] = src[jl * 256 + c];
        }
    }
    __syncthreads();

    uint32_t sAdst[NBUF];
    #pragma unroll
    for (int v = 0; v < NBUF; ++v)
        sAdst[v] = smem_u32(sW + W_HALVES + v * ACH_HALVES);
    const uint32_t wB = smem_u32(sW);
    const int warp = tid >> 5, lane = tid & 31;
    const int gr = lane >> 2, q = lane & 3;
    const int r0 = warp * 16;                 // 8 warps cover M=128
    const int lrow = (lane & 7) | (lane & 8);
    const int lc16 = (lane >> 4) & 1;
    const uint32_t aOff = (uint32_t)((r0 + lrow) * 272 + lc16 * 16);
    uint32_t aBase[NBUF];
    #pragma unroll
    for (int v = 0; v < NBUF; ++v) aBase[v] = sAdst[v] + aOff;
    // ldmatrix weight bases
    const uint32_t bL0_0 = wB + (uint32_t)(lrow * 2064 + lc16 * 16);           // j 0..15
    const uint32_t bL0_1 = wB + (uint32_t)((16 + lrow) * 2064 + lc16 * 16);    // j 16..31
    const uint32_t bL1   = wB + (uint32_t)(lrow * 4112 + lc16 * 16);           // j 0..15
    const int st_r = tid >> 4;                // staging rows st_r + j*16
    const int st_c = tid & 15;

    for (int s = 0; s <= cT; ++s) {
        const int p = s & 1;
        if (isL0) {
            if (s < cT) {
                const uint4* gsrc = (const uint4*)g_h0[p];
                #pragma unroll
                for (int pc = 0; pc < 2; ++pc) {
                    #pragma unroll
                    for (int j = 0; j < 8; ++j) {
                        const int r = st_r + j * 16;
                        cp16(sAdst[pc] + (uint32_t)(r * 17 + st_c) * 16,
                             gsrc + r * 128 + pc * 16 + st_c);
                    }
                    CP_COMMIT();
                }
                float c[2][4][4] = {};
                #pragma unroll 1
                for (int kc = 0; kc < 8; ++kc) {
                    CP_WAIT(1);
                    __syncthreads();
                    const int kn = kc + 2;
                    if (kn < 8) {
                        const uint32_t d = sAdst[kn % NBUF];
                        #pragma unroll
                        for (int j = 0; j < 8; ++j) {
                            const int r = st_r + j * 16;
                            cp16(d + (uint32_t)(r * 17 + st_c) * 16,
                                 gsrc + r * 128 + kn * 16 + st_c);
                        }
                    }
                    CP_COMMIT();   // may be empty
                    const uint32_t Ab = aBase[kc % NBUF];
                    const uint32_t kcb = (uint32_t)kc * 256;
                    #pragma unroll
                    for (int i = 0; i < 8; ++i) {
                        float (*cc)[4] = c[i & 1];
                        unsigned a[4], b0[4], b1[4];
                        ldsm4(a, Ab + i * 32);
                        ldsm4(b0, bL0_0 + kcb + i * 32);
                        ldsm4(b1, bL0_1 + kcb + i * 32);
                        mma_m16n8k16(cc[0], a, b0[0], b0[2]);
                        mma_m16n8k16(cc[1], a, b0[1], b0[3]);
                        mma_m16n8k16(cc[2], a, b1[0], b1[2]);
                        mma_m16n8k16(cc[3], a, b1[1], b1[3]);
                    }
                }
                // epilogue
                const int jb = bx * 32;
                const int row0 = r0 + gr, row8 = row0 + 8;
                const float xv0 = g_xT[s * cB + row0];
                const float xv8 = g_xT[s * cB + row8];
                __half* outh = g_h0[1 - p];
                const bool fin = (s == cT - 1);
                #pragma unroll
                for (int nf = 0; nf < 4; ++nf) {
                    const int j = jb + nf * 8 + 2 * q;
                    const float w0a = g_w0[j], w0b = g_w0[j + 1];
                    const float ba = g_b0[j], bb = g_b0[j + 1];
                    const float h00 = tanhf(c[0][nf][0] + c[1][nf][0] + xv0 * w0a + ba);
                    const float h01 = tanhf(c[0][nf][1] + c[1][nf][1] + xv0 * w0b + bb);
                    const float h08 = tanhf(c[0][nf][2] + c[1][nf][2] + xv8 * w0a + ba);
                    const float h09 = tanhf(c[0][nf][3] + c[1][nf][3] + xv8 * w0b + bb);
                    const int i0 = row0 * cH + j;
                    const int i8 = row8 * cH + j;
                    *(__half2*)(outh + i0) = __floats2half2_rn(h00, h01);
                    *(__half2*)(outh + i8) = __floats2half2_rn(h08, h09);
                    if (fin) {
                        *(float2*)(g_h0f + i0) = make_float2(h00, h01);
                        *(float2*)(g_h0f + i8) = make_float2(h08, h09);
                    }
                }
            }
        } else {
            if (s >= 1) {
                const uint4* gh0 = (const uint4*)g_h0[p];
                const uint4* gh1 = (const uint4*)g_h1[p];
                #pragma unroll
                for (int pc = 0; pc < 2; ++pc) {
                    #pragma unroll
                    for (int j = 0; j < 8; ++j) {
                        const int r = st_r + j * 16;
                        cp16(sAdst[pc] + (uint32_t)(r * 17 + st_c) * 16,
                             gh0 + r * 128 + pc * 16 + st_c);
                    }
                    CP_COMMIT();
                }
                float c[2][2][4] = {};
                #pragma unroll 1
                for (int kc = 0; kc < 16; ++kc) {
                    CP_WAIT(1);
                    __syncthreads();
                    const int kn = kc + 2;
                    if (kn < 16) {
                        const uint4* gsrc = (kn < 8) ? gh0 : gh1;
                        const int kloc = kn & 7;
                        const uint32_t d = sAdst[kn % NBUF];
                        #pragma unroll
                        for (int j = 0; j < 8; ++j) {
                            const int r = st_r + j * 16;
                            cp16(d + (uint32_t)(r * 17 + st_c) * 16,
                                 gsrc + r * 128 + kloc * 16 + st_c);
                        }
                    }
                    CP_COMMIT();   // may be empty
                    const uint32_t Ab = aBase[kc % NBUF];
                    const uint32_t kcb = (uint32_t)kc * 256;
                    #pragma unroll
                    for (int i = 0; i < 8; ++i) {
                        float (*cc)[4] = c[i & 1];
                        unsigned a[4], b[4];
                        ldsm4(a, Ab + i * 32);
                        ldsm4(b, bL1 + kcb + i * 32);
                        mma_m16n8k16(cc[0], a, b[0], b[2]);
                        mma_m16n8k16(cc[1], a, b[1], b[3]);
                    }
                }
                // epilogue
                const int jb = (bx - NL0) * 16;
                const int row0 = r0 + gr, row8 = row0 + 8;
                __half* outh = g_h1[1 - p];
                __half* H1t = g_H1 + (size_t)(s - 1) * cB * cH;
                const bool fin = (s == cT);
                #pragma unroll
                for (int nf = 0; nf < 2; ++nf) {
                    const int j = jb + nf * 8 + 2 * q;
                    const float ba = g_b1[j], bb = g_b1[j + 1];
                    const float h10 = tanhf(c[0][nf][0] + c[1][nf][0] + ba);
                    const float h11 = tanhf(c[0][nf][1] + c[1][nf][1] + bb);
                    const float h12 = tanhf(c[0][nf][2] + c[1][nf][2] + ba);
                    const float h13 = tanhf(c[0][nf][3] + c[1][nf][3] + bb);
                    const int i0 = row0 * cH + j;
                    const int i8 = row8 * cH + j;
                    const __half2 lo = __floats2half2_rn(h10, h11);
                    const __half2 hi = __floats2half2_rn(h12, h13);
                    *(__half2*)(outh + i0) = lo;
                    *(__half2*)(outh + i8) = hi;
                    *(__half2*)(H1t + i0) = lo;
                    *(__half2*)(H1t + i8) = hi;
                    if (fin) {
                        *(float2*)(g_h1f + i0) = make_float2(h10, h11);
                        *(float2*)(g_h1f + i8) = make_float2(h12, h13);
                    }
                }
            }
        }
        grid_barrier(NREC, (s == cT) ? 0u : (unsigned)(s + 2), (unsigned)(s + 1));
    }

    // final hidden states (CTAs 0..7), then join the GEMM queue
    if (bx < 8 && do_states) {
        const size_t off = (size_t)cB * cT * cV;
        for (int i = bx * 256 + tid; i < cB * cH; i += 8 * 256) {
            out[off + i] = g_h0f[i];
            out[off + cB * cH + i] = g_h1f[i];
        }
    }
    gemm_worker(smem_raw, bfc, out);
}

extern "C" void kernel_launch(void* const* d_in, const int* in_sizes, int n_in,
                              void* d_out, int out_size) {
    const float* x    = (const float*)d_in[0];
    const float* Wih0 = (const float*)d_in[1];
    const float* Whh0 = (const float*)d_in[2];
    const float* bih0 = (const float*)d_in[3];
    const float* bhh0 = (const float*)d_in[4];
    const float* Wih1 = (const float*)d_in[5];
    const float* Whh1 = (const float*)d_in[6];
    const float* bih1 = (const float*)d_in[7];
    const float* bhh1 = (const float*)d_in[8];
    const float* Wfc  = (const float*)d_in[9];
    const float* bfc  = (const float*)d_in[10];
    float* out = (float*)d_out;

    cudaFuncSetAttribute(k_fused, cudaFuncAttributeMaxDynamicSharedMemorySize, SMEM_F);

    const long long need = (long long)cB * cT * cV + 2LL * cB * cH;
    const int do_states = ((long long)out_size >= need) ? 1 : 0;

    k_fused<<<GRID_F, 256, SMEM_F>>>(x, Wih0, Whh0, bih0, bhh0,
                                     Wih1, Whh1, bih1, bhh1,
                                     Wfc, bfc, out, do_states);
}